// round 15
// baseline (speedup 1.0000x reference)
#include <cuda_runtime.h>
#include <cuda_bf16.h>
#include <cuda_fp16.h>
#include <cstdint>
#include <cstddef>

#define NT 512
#define NG 16384
#define DM 512
#define NH 8
#define DK 64
#define HD 512

// ---------------- scratch (static device memory) ----------------
__device__ __half g_Zf[3][NG][DM];                   // inputs, fp16
__device__ __half g_Wf[6][DM][HD];                   // 0-2: Wk_{seq,exp,txt}, 3-5: Wq_*
__device__ __half g_Qf[3][NT][HD];                   // Q * 0.125, fp16
__device__ __half g_Kf[3][NG][HD];                   // K, fp16
__device__ __half g_P[NH][NT][NG];                   // exp(u) in fp16
__device__ float g_part[NH][NT][512];                // per-32g-chunk sum(exp(u))
__device__ float g_invz[NH][NT];

// ---------------- ptx helpers ----------------
__device__ __forceinline__ uint32_t s2u(const void* p) {
    return (uint32_t)__cvta_generic_to_shared(p);
}
__device__ __forceinline__ void ldsm4(uint32_t* r, uint32_t a) {
    asm volatile("ldmatrix.sync.aligned.m8n8.x4.shared.b16 {%0,%1,%2,%3},[%4];\n"
                 : "=r"(r[0]), "=r"(r[1]), "=r"(r[2]), "=r"(r[3]) : "r"(a));
}
__device__ __forceinline__ void ldsm4t(uint32_t* r, uint32_t a) {
    asm volatile("ldmatrix.sync.aligned.m8n8.x4.trans.shared.b16 {%0,%1,%2,%3},[%4];\n"
                 : "=r"(r[0]), "=r"(r[1]), "=r"(r[2]), "=r"(r[3]) : "r"(a));
}
__device__ __forceinline__ void mma_f16(float* d, const uint32_t* a, const uint32_t* b) {
    asm volatile("mma.sync.aligned.m16n8k16.row.col.f32.f16.f16.f32 "
                 "{%0,%1,%2,%3},{%4,%5,%6,%7},{%8,%9},{%0,%1,%2,%3};\n"
                 : "+f"(d[0]), "+f"(d[1]), "+f"(d[2]), "+f"(d[3])
                 : "r"(a[0]), "r"(a[1]), "r"(a[2]), "r"(a[3]), "r"(b[0]), "r"(b[1]));
}
__device__ __forceinline__ void cpa16(uint32_t s, const void* g) {
    asm volatile("cp.async.cg.shared.global [%0], [%1], 16;\n" :: "r"(s), "l"(g) : "memory");
}
__device__ __forceinline__ float frcp(float x) {
    float r;
    asm("rcp.approx.f32 %0, %1;" : "=f"(r) : "f"(x));
    return r;
}
#define CP_COMMIT() asm volatile("cp.async.commit_group;\n" ::: "memory")
#define CP_WAIT0()  asm volatile("cp.async.wait_group 0;\n" ::: "memory")

// =====================================================================
// Convert fp32 -> fp16 for z (3) and W (6), plus passthrough copies.
// =====================================================================
__global__ void split_kernel(const float4* __restrict__ za, const float4* __restrict__ zb,
                             const float4* __restrict__ zc,
                             const float4* __restrict__ w0, const float4* __restrict__ w1,
                             const float4* __restrict__ w2, const float4* __restrict__ w3,
                             const float4* __restrict__ w4, const float4* __restrict__ w5,
                             const float4* __restrict__ htf, const float4* __restrict__ hg,
                             float4* __restrict__ outc)
{
    const int NZ4 = NG * DM / 4;
    const int NW4 = DM * HD / 4;
    const int NA4 = NT * DM / 4;
    const int NC4 = NA4 + NG * DM / 4;
    const int TOT = 3 * NZ4 + 6 * NW4 + NC4;
    for (int i = blockIdx.x * blockDim.x + threadIdx.x; i < TOT; i += gridDim.x * blockDim.x) {
        if (i >= 3 * NZ4 + 6 * NW4) {
            const int j = i - 3 * NZ4 - 6 * NW4;
            outc[j] = (j < NA4) ? htf[j] : hg[j - NA4];
            continue;
        }
        float4 v; __half2* dst;
        if (i < 3 * NZ4) {
            const int e = i / NZ4, j = i - e * NZ4;
            v = (e == 0 ? za : e == 1 ? zb : zc)[j];
            dst = (__half2*)&g_Zf[e][0][0] + (size_t)j * 2;
        } else {
            const int k = i - 3 * NZ4;
            const int w = k / NW4, j = k - w * NW4;
            const float4* src = w == 0 ? w0 : w == 1 ? w1 : w == 2 ? w2 : w == 3 ? w3 : w == 4 ? w4 : w5;
            v = src[j];
            dst = (__half2*)&g_Wf[w][0][0] + (size_t)j * 2;
        }
        dst[0] = __floats2half2_rn(v.x, v.y);
        dst[1] = __floats2half2_rn(v.z, v.w);
    }
}

// =====================================================================
// Projection GEMM, single-term fp16 MMA, cp.async double-buffered.
// Merged K+Q launch (z >= 3 -> Q). (unchanged known-good)
// =====================================================================
#define PASZ (128 * 40)
#define PBSZ (32 * 136)
#define PROJ_SMEM ((2 * PASZ + 2 * PBSZ) * 2)   // 37888 bytes

__global__ __launch_bounds__(256, 2)
void proj_mma(const int* __restrict__ idx)
{
    const int isQ = blockIdx.z >= 3;
    const int e = isQ ? (blockIdx.z - 3) : blockIdx.z;
    const int m0 = blockIdx.x * 128, n0 = blockIdx.y * 128;
    if (isQ && m0 >= NT) return;
    const __half* Z = &g_Zf[e][0][0];
    const __half* W = &g_Wf[(isQ ? 3 : 0) + e][0][0];
    __half* Cf = isQ ? &g_Qf[e][0][0] : &g_Kf[e][0][0];
    const float cscale = isQ ? 0.125f : 1.0f;

    extern __shared__ char sm[];
    __half* sA = (__half*)sm;
    __half* sB = sA + 2 * PASZ;

    const int tid = threadIdx.x;
    const int lane = tid & 31, warp = tid >> 5;
    const int wm = warp >> 2, wn = warp & 3;

    const int l0 = tid, l1 = tid + 256;
    const int ar0 = l0 >> 2, ac0 = (l0 & 3) << 3;
    const int ar1 = l1 >> 2, ac1 = (l1 & 3) << 3;
    const int gr0 = isQ ? idx[m0 + ar0] : (m0 + ar0);
    const int gr1 = isQ ? idx[m0 + ar1] : (m0 + ar1);
    const int br0 = l0 >> 4, bc0 = (l0 & 15) << 3;
    const int br1 = l1 >> 4, bc1 = (l1 & 15) << 3;

    auto prefetch = [&](int kt, int b) {
        const int k0 = kt * 32;
        cpa16(s2u(&sA[b * PASZ + ar0 * 40 + ac0]), Z + (size_t)gr0 * DM + k0 + ac0);
        cpa16(s2u(&sA[b * PASZ + ar1 * 40 + ac1]), Z + (size_t)gr1 * DM + k0 + ac1);
        cpa16(s2u(&sB[b * PBSZ + br0 * 136 + bc0]), W + (size_t)(k0 + br0) * HD + n0 + bc0);
        cpa16(s2u(&sB[b * PBSZ + br1 * 136 + bc1]), W + (size_t)(k0 + br1) * HD + n0 + bc1);
    };

    float acc[4][4][4];
    #pragma unroll
    for (int i = 0; i < 4; i++)
        #pragma unroll
        for (int j = 0; j < 4; j++)
            #pragma unroll
            for (int k = 0; k < 4; k++) acc[i][j][k] = 0.f;

    prefetch(0, 0);
    CP_COMMIT();
    CP_WAIT0();
    __syncthreads();

    int cur = 0;
    for (int kt = 0; kt < 16; kt++) {
        if (kt < 15) { prefetch(kt + 1, cur ^ 1); CP_COMMIT(); }

        const __half* cA = sA + cur * PASZ;
        const __half* cB = sB + cur * PBSZ;

        #pragma unroll
        for (int kk = 0; kk < 32; kk += 16) {
            uint32_t a[4][4], b[4][2];
            #pragma unroll
            for (int mi = 0; mi < 4; mi++) {
                const int row = wm * 64 + mi * 16 + (lane & 15);
                const int col = kk + ((lane >> 4) << 3);
                ldsm4(a[mi], s2u(&cA[row * 40 + col]));
            }
            #pragma unroll
            for (int n16 = 0; n16 < 2; n16++) {
                const int row = kk + (lane & 15);
                const int col = wn * 32 + n16 * 16 + ((lane >> 4) << 3);
                uint32_t t[4];
                ldsm4t(t, s2u(&cB[row * 136 + col]));
                b[n16 * 2 + 0][0] = t[0]; b[n16 * 2 + 0][1] = t[1];
                b[n16 * 2 + 1][0] = t[2]; b[n16 * 2 + 1][1] = t[3];
            }
            #pragma unroll
            for (int mi = 0; mi < 4; mi++)
                #pragma unroll
                for (int nf = 0; nf < 4; nf++)
                    mma_f16(acc[mi][nf], a[mi], b[nf]);
        }

        if (kt < 15) {
            CP_WAIT0();
            __syncthreads();
            cur ^= 1;
        }
    }

    #pragma unroll
    for (int mi = 0; mi < 4; mi++) {
        const int r0 = m0 + wm * 64 + mi * 16 + (lane >> 2);
        #pragma unroll
        for (int nf = 0; nf < 4; nf++) {
            const int cc = n0 + wn * 32 + nf * 8 + ((lane & 3) << 1);
            #pragma unroll
            for (int rh = 0; rh < 2; rh++) {
                const int r = r0 + rh * 8;
                const float x0 = acc[mi][nf][rh * 2 + 0] * cscale;
                const float x1 = acc[mi][nf][rh * 2 + 1] * cscale;
                *(__half2*)&Cf[(size_t)r * HD + cc] = __floats2half2_rn(x0, x1);
            }
        }
    }
}

// =====================================================================
// Fused scores (single-term fp16 MMA) + gate + softmax partials + alpha means.
// CTA 64t x 64g, 256 threads (8 warps: wt=warp>>1 in 0..3, wg=warp&1),
// warp tile 16x32, 2 CTAs/SM. P stores quad-transposed into STG.128.
// u_mean recovered from log(P) in amean.
// =====================================================================
#define QMAT  9216                   // 64*72*2
#define STAGE (6 * QMAT)             // 3 Q + 3 K = 55296
#define SCORE_SMEM (2 * STAGE)       // 110592
#define LOG2E 1.4426950408889634f

__global__ __launch_bounds__(256, 2)
void score_cp(const float* __restrict__ gateW, const float* __restrict__ gateB,
              float* __restrict__ out_amean)
{
    extern __shared__ char sm[];

    const int tid = threadIdx.x;
    const int lane = tid & 31, warp = tid >> 5;
    const int wt = warp >> 1, wg = warp & 1;
    const int t0 = blockIdx.x * 64;
    const int g0 = blockIdx.y * 64;
    const int q = lane & 3;

    float acc_a0[16], acc_a1[16];
    #pragma unroll
    for (int i = 0; i < 16; i++) { acc_a0[i] = 0.f; acc_a1[i] = 0.f; }

    const int prow = tid >> 3, pc8 = (tid & 7) << 3;   // prow 0..31
    auto prefetch = [&](int h, int stg) {
        char* base = sm + stg * STAGE;
        #pragma unroll
        for (int e = 0; e < 3; e++) {
            char* qb = base + e * QMAT;
            char* kb = base + (3 + e) * QMAT;
            #pragma unroll
            for (int j = 0; j < 2; j++) {
                const int row = prow + j * 32;
                cpa16(s2u(qb + (row * 72 + pc8) * 2),
                      &g_Qf[e][0][0] + (size_t)(t0 + row) * HD + h * DK + pc8);
                cpa16(s2u(kb + (row * 72 + pc8) * 2),
                      &g_Kf[e][0][0] + (size_t)(g0 + row) * HD + h * DK + pc8);
            }
        }
    };

    prefetch(0, 0);
    CP_COMMIT();

    for (int h = 0; h < NH; h++) {
        const int stg = h & 1;
        CP_WAIT0();
        __syncthreads();
        if (h < NH - 1) { prefetch(h + 1, stg ^ 1); CP_COMMIT(); }

        const __half* tiles = (const __half*)(sm + stg * STAGE);

        float s[3][4][4];
        #pragma unroll
        for (int e = 0; e < 3; e++)
            #pragma unroll
            for (int c = 0; c < 4; c++)
                #pragma unroll
                for (int k = 0; k < 4; k++) s[e][c][k] = 0.f;

        #pragma unroll
        for (int e = 0; e < 3; e++) {
            const __half* Qf = tiles + e * (QMAT / 2);
            const __half* Kf = tiles + (3 + e) * (QMAT / 2);
            #pragma unroll
            for (int kk = 0; kk < 64; kk += 16) {
                const int col = kk + ((lane >> 4) << 3);
                uint32_t a[4];
                {
                    const int row = wt * 16 + (lane & 15);
                    ldsm4(a, s2u(&Qf[row * 72 + col]));
                }
                uint32_t b[4][2];
                #pragma unroll
                for (int n16 = 0; n16 < 2; n16++) {
                    const int row = wg * 32 + n16 * 16 + (lane & 15);
                    uint32_t kr[4];
                    ldsm4(kr, s2u(&Kf[row * 72 + col]));
                    b[n16 * 2 + 0][0] = kr[0]; b[n16 * 2 + 0][1] = kr[2];
                    b[n16 * 2 + 1][0] = kr[1]; b[n16 * 2 + 1][1] = kr[3];
                }
                #pragma unroll
                for (int nf = 0; nf < 4; nf++)
                    mma_f16(s[e][nf], a, b[nf]);
            }
        }

        // ---- gate + softmax-stats epilogue (relative to l2; log2 domain) ----
        const float w00 = gateW[h*9+0] * LOG2E, w01 = gateW[h*9+1] * LOG2E, w02 = gateW[h*9+2] * LOG2E;
        const float w10 = gateW[h*9+3] * LOG2E, w11 = gateW[h*9+4] * LOG2E, w12 = gateW[h*9+5] * LOG2E;
        const float w20 = gateW[h*9+6] * LOG2E, w21 = gateW[h*9+7] * LOG2E, w22 = gateW[h*9+8] * LOG2E;
        const float gb0 = gateB[h*3+0] * LOG2E, gb1 = gateB[h*3+1] * LOG2E, gb2 = gateB[h*3+2] * LOG2E;

        #pragma unroll
        for (int rh = 0; rh < 2; rh++) {
            const int tl = wt * 16 + (lane >> 2) + rh * 8;
            float zs = 0.f;
            uint32_t ph[4];
            #pragma unroll
            for (int nf = 0; nf < 4; nf++) {
                float eu2[2];
                #pragma unroll
                for (int p = 0; p < 2; p++) {
                    const int fi = rh * 8 + nf * 2 + p;
                    const float s0 = s[0][nf][rh * 2 + p];
                    const float s1 = s[1][nf][rh * 2 + p];
                    const float s2 = s[2][nf][rh * 2 + p];
                    const float l0 = fmaf(s0, w00, fmaf(s1, w10, fmaf(s2, w20, gb0)));
                    const float l1 = fmaf(s0, w01, fmaf(s1, w11, fmaf(s2, w21, gb1)));
                    const float l2 = fmaf(s0, w02, fmaf(s1, w12, fmaf(s2, w22, gb2)));
                    const float r0 = exp2f(l0 - l2);
                    const float r1 = exp2f(l1 - l2);
                    const float inv = frcp(r0 + r1 + 1.0f);
                    const float u = fmaf(r0, s0, fmaf(r1, s1, s2)) * inv;
                    const float eu = exp2f(u * LOG2E);
                    eu2[p] = eu;
                    zs += eu;
                    acc_a0[fi] += r0 * inv;
                    acc_a1[fi] += r1 * inv;
                }
                __half2 hp = __floats2half2_rn(eu2[0], eu2[1]);
                ph[nf] = *(uint32_t*)&hp;
            }
            // quad-transpose: v[j] = thread_{quad j}'s ph[q]; then one STG.128
            uint32_t v[4];
            v[q] = ph[q];
            #pragma unroll
            for (int r = 1; r < 4; r++)
                v[q ^ r] = __shfl_xor_sync(0xffffffffu, ph[q ^ r], r, 4);
            uint4 pk; pk.x = v[0]; pk.y = v[1]; pk.z = v[2]; pk.w = v[3];
            *(uint4*)&g_P[h][t0 + tl][g0 + wg * 32 + q * 8] = pk;

            zs += __shfl_xor_sync(0xffffffffu, zs, 1);
            zs += __shfl_xor_sync(0xffffffffu, zs, 2);
            if (q == 0)
                g_part[h][t0 + tl][blockIdx.y * 2 + wg] = zs;
        }
    }

    // alpha means from register accumulators
    #pragma unroll
    for (int rh = 0; rh < 2; rh++) {
        const int tl = wt * 16 + (lane >> 2) + rh * 8;
        #pragma unroll
        for (int nf = 0; nf < 4; nf++) {
            const int gl = wg * 32 + nf * 8 + (q << 1);
            const size_t o = (size_t)(t0 + tl) * NG + g0 + gl;
            const int f0 = rh * 8 + nf * 2;
            const float a00 = acc_a0[f0]     * 0.125f;
            const float a10 = acc_a1[f0]     * 0.125f;
            const float a01 = acc_a0[f0 + 1] * 0.125f;
            const float a11 = acc_a1[f0 + 1] * 0.125f;
            float2* ap = (float2*)(out_amean + o * 3);
            ap[0] = make_float2(a00, a10);
            ap[1] = make_float2(1.0f - a00 - a10, a01);
            ap[2] = make_float2(a11, 1.0f - a01 - a11);
        }
    }
}

// =====================================================================
// Reduce per-chunk partial sums -> 1/Z per (h, t). One warp per row.
// =====================================================================
__global__ void stats_kernel()
{
    const int gt   = blockIdx.x * blockDim.x + threadIdx.x;
    const int wid  = gt >> 5;
    const int lane = threadIdx.x & 31;
    if (wid >= NH * NT) return;
    const int h = wid >> 9;
    const int t = wid & (NT - 1);

    float z = 0.f;
    #pragma unroll
    for (int j = 0; j < 16; j++)
        z += g_part[h][t][lane + 32 * j];
    #pragma unroll
    for (int off = 16; off; off >>= 1)
        z += __shfl_xor_sync(0xffffffffu, z, off);
    if (lane == 0) g_invz[h][t] = 1.0f / z;
}

// =====================================================================
// A_mean[t,g] = (1/8) * sum_h p / Z;  u_mean[t,g] = (1/8) * sum_h log(p).
// =====================================================================
__global__ void amean_kernel(float* __restrict__ out_A, float* __restrict__ out_u)
{
    const int t = blockIdx.y;
    const int g = (blockIdx.x * 256 + threadIdx.x) * 4;
    __shared__ float st[NH];
    if (threadIdx.x < NH) st[threadIdx.x] = g_invz[threadIdx.x][t];
    __syncthreads();
    float4 acc = make_float4(0.f, 0.f, 0.f, 0.f);
    float4 um  = make_float4(0.f, 0.f, 0.f, 0.f);
    #pragma unroll
    for (int h = 0; h < NH; h++) {
        const __half2* pp = (const __half2*)&g_P[h][t][g];
        const float2 f0 = __half22float2(pp[0]);
        const float2 f1 = __half22float2(pp[1]);
        const float iz = st[h];
        acc.x = fmaf(f0.x, iz, acc.x);
        acc.y = fmaf(f0.y, iz, acc.y);
        acc.z = fmaf(f1.x, iz, acc.z);
        acc.w = fmaf(f1.y, iz, acc.w);
        um.x += __log2f(f0.x);
        um.y += __log2f(f0.y);
        um.z += __log2f(f1.x);
        um.w += __log2f(f1.y);
    }
    acc.x *= 0.125f; acc.y *= 0.125f; acc.z *= 0.125f; acc.w *= 0.125f;
    const float us = 0.125f / LOG2E;
    um.x *= us; um.y *= us; um.z *= us; um.w *= us;
    *(float4*)&out_A[(size_t)t * NG + g] = acc;
    *(float4*)&out_u[(size_t)t * NG + g] = um;
}

// =====================================================================
extern "C" void kernel_launch(void* const* d_in, const int* in_sizes, int n_in,
                              void* d_out, int out_size)
{
    const float* H_TF   = (const float*)d_in[0];
    const float* H_G    = (const float*)d_in[1];
    const float* z_exp  = (const float*)d_in[2];
    const float* z_seq  = (const float*)d_in[3];
    const float* z_txt  = (const float*)d_in[4];
    const int*   tf_idx = (const int*)  d_in[5];
    const float* Wq_seq = (const float*)d_in[6];
    const float* Wk_seq = (const float*)d_in[7];
    const float* Wq_exp = (const float*)d_in[8];
    const float* Wk_exp = (const float*)d_in[9];
    const float* Wq_txt = (const float*)d_in[10];
    const float* Wk_txt = (const float*)d_in[11];
    const float* gateW  = (const float*)d_in[12];
    const float* gateB  = (const float*)d_in[13];
    float* out = (float*)d_out;

    float* out_A  = out + (size_t)NT * DM + (size_t)NG * DM;
    float* out_u  = out_A + (size_t)NT * NG;
    float* out_al = out_u + (size_t)NT * NG;

    cudaFuncSetAttribute(proj_mma, cudaFuncAttributeMaxDynamicSharedMemorySize, PROJ_SMEM);
    cudaFuncSetAttribute(score_cp, cudaFuncAttributeMaxDynamicSharedMemorySize, SCORE_SMEM);

    // evidence order: e0 = seq (bind), e1 = exp (coexpr), e2 = txt (know)
    split_kernel<<<4096, 256>>>((const float4*)z_seq, (const float4*)z_exp, (const float4*)z_txt,
                                (const float4*)Wk_seq, (const float4*)Wk_exp, (const float4*)Wk_txt,
                                (const float4*)Wq_seq, (const float4*)Wq_exp, (const float4*)Wq_txt,
                                (const float4*)H_TF, (const float4*)H_G, (float4*)out);

    proj_mma<<<dim3(NG / 128, 4, 6), 256, PROJ_SMEM>>>(tf_idx);

    score_cp<<<dim3(NT / 64, NG / 64), 256, SCORE_SMEM>>>(gateW, gateB, out_al);

    stats_kernel<<<(NH * NT * 32) / 256, 256>>>();

    amean_kernel<<<dim3(NG / 1024, NT), 256>>>(out_A, out_u);
}

// round 16
// speedup vs baseline: 1.1004x; 1.1004x over previous
#include <cuda_runtime.h>
#include <cuda_bf16.h>
#include <cuda_fp16.h>
#include <cstdint>
#include <cstddef>

#define NT 512
#define NG 16384
#define DM 512
#define NH 8
#define DK 64
#define HD 512

// ---------------- scratch (static device memory) ----------------
__device__ __half g_Zf[3][NG][DM];                   // inputs, fp16
__device__ __half g_Wf[6][DM][HD];                   // 0-2: Wk_{seq,exp,txt}, 3-5: Wq_*
__device__ __half g_Qf[3][NT][HD];                   // Q * 0.125, fp16
__device__ __half g_Kf[3][NG][HD];                   // K, fp16
__device__ __half g_P[NH][NT][NG];                   // exp(u) in fp16
__device__ float g_part[NH][NT][512];                // per-32g-chunk sum(exp(u))
__device__ float g_invz[NH][NT];

// ---------------- ptx helpers ----------------
__device__ __forceinline__ uint32_t s2u(const void* p) {
    return (uint32_t)__cvta_generic_to_shared(p);
}
__device__ __forceinline__ void ldsm4(uint32_t* r, uint32_t a) {
    asm volatile("ldmatrix.sync.aligned.m8n8.x4.shared.b16 {%0,%1,%2,%3},[%4];\n"
                 : "=r"(r[0]), "=r"(r[1]), "=r"(r[2]), "=r"(r[3]) : "r"(a));
}
__device__ __forceinline__ void ldsm4t(uint32_t* r, uint32_t a) {
    asm volatile("ldmatrix.sync.aligned.m8n8.x4.trans.shared.b16 {%0,%1,%2,%3},[%4];\n"
                 : "=r"(r[0]), "=r"(r[1]), "=r"(r[2]), "=r"(r[3]) : "r"(a));
}
__device__ __forceinline__ void mma_f16(float* d, const uint32_t* a, const uint32_t* b) {
    asm volatile("mma.sync.aligned.m16n8k16.row.col.f32.f16.f16.f32 "
                 "{%0,%1,%2,%3},{%4,%5,%6,%7},{%8,%9},{%0,%1,%2,%3};\n"
                 : "+f"(d[0]), "+f"(d[1]), "+f"(d[2]), "+f"(d[3])
                 : "r"(a[0]), "r"(a[1]), "r"(a[2]), "r"(a[3]), "r"(b[0]), "r"(b[1]));
}
__device__ __forceinline__ void cpa16(uint32_t s, const void* g) {
    asm volatile("cp.async.cg.shared.global [%0], [%1], 16;\n" :: "r"(s), "l"(g) : "memory");
}
__device__ __forceinline__ float frcp(float x) {
    float r;
    asm("rcp.approx.f32 %0, %1;" : "=f"(r) : "f"(x));
    return r;
}
#define CP_COMMIT() asm volatile("cp.async.commit_group;\n" ::: "memory")
#define CP_WAIT0()  asm volatile("cp.async.wait_group 0;\n" ::: "memory")

// =====================================================================
// Convert fp32 -> fp16 for z (3) and W (6), plus passthrough copies.
// =====================================================================
__global__ void split_kernel(const float4* __restrict__ za, const float4* __restrict__ zb,
                             const float4* __restrict__ zc,
                             const float4* __restrict__ w0, const float4* __restrict__ w1,
                             const float4* __restrict__ w2, const float4* __restrict__ w3,
                             const float4* __restrict__ w4, const float4* __restrict__ w5,
                             const float4* __restrict__ htf, const float4* __restrict__ hg,
                             float4* __restrict__ outc)
{
    const int NZ4 = NG * DM / 4;
    const int NW4 = DM * HD / 4;
    const int NA4 = NT * DM / 4;
    const int NC4 = NA4 + NG * DM / 4;
    const int TOT = 3 * NZ4 + 6 * NW4 + NC4;
    for (int i = blockIdx.x * blockDim.x + threadIdx.x; i < TOT; i += gridDim.x * blockDim.x) {
        if (i >= 3 * NZ4 + 6 * NW4) {
            const int j = i - 3 * NZ4 - 6 * NW4;
            outc[j] = (j < NA4) ? htf[j] : hg[j - NA4];
            continue;
        }
        float4 v; __half2* dst;
        if (i < 3 * NZ4) {
            const int e = i / NZ4, j = i - e * NZ4;
            v = (e == 0 ? za : e == 1 ? zb : zc)[j];
            dst = (__half2*)&g_Zf[e][0][0] + (size_t)j * 2;
        } else {
            const int k = i - 3 * NZ4;
            const int w = k / NW4, j = k - w * NW4;
            const float4* src = w == 0 ? w0 : w == 1 ? w1 : w == 2 ? w2 : w == 3 ? w3 : w == 4 ? w4 : w5;
            v = src[j];
            dst = (__half2*)&g_Wf[w][0][0] + (size_t)j * 2;
        }
        dst[0] = __floats2half2_rn(v.x, v.y);
        dst[1] = __floats2half2_rn(v.z, v.w);
    }
}

// =====================================================================
// Projection GEMM, single-term fp16 MMA, cp.async double-buffered.
// Merged K+Q launch (z >= 3 -> Q). (unchanged known-good)
// =====================================================================
#define PASZ (128 * 40)
#define PBSZ (32 * 136)
#define PROJ_SMEM ((2 * PASZ + 2 * PBSZ) * 2)   // 37888 bytes

__global__ __launch_bounds__(256, 2)
void proj_mma(const int* __restrict__ idx)
{
    const int isQ = blockIdx.z >= 3;
    const int e = isQ ? (blockIdx.z - 3) : blockIdx.z;
    const int m0 = blockIdx.x * 128, n0 = blockIdx.y * 128;
    if (isQ && m0 >= NT) return;
    const __half* Z = &g_Zf[e][0][0];
    const __half* W = &g_Wf[(isQ ? 3 : 0) + e][0][0];
    __half* Cf = isQ ? &g_Qf[e][0][0] : &g_Kf[e][0][0];
    const float cscale = isQ ? 0.125f : 1.0f;

    extern __shared__ char sm[];
    __half* sA = (__half*)sm;
    __half* sB = sA + 2 * PASZ;

    const int tid = threadIdx.x;
    const int lane = tid & 31, warp = tid >> 5;
    const int wm = warp >> 2, wn = warp & 3;

    const int l0 = tid, l1 = tid + 256;
    const int ar0 = l0 >> 2, ac0 = (l0 & 3) << 3;
    const int ar1 = l1 >> 2, ac1 = (l1 & 3) << 3;
    const int gr0 = isQ ? idx[m0 + ar0] : (m0 + ar0);
    const int gr1 = isQ ? idx[m0 + ar1] : (m0 + ar1);
    const int br0 = l0 >> 4, bc0 = (l0 & 15) << 3;
    const int br1 = l1 >> 4, bc1 = (l1 & 15) << 3;

    auto prefetch = [&](int kt, int b) {
        const int k0 = kt * 32;
        cpa16(s2u(&sA[b * PASZ + ar0 * 40 + ac0]), Z + (size_t)gr0 * DM + k0 + ac0);
        cpa16(s2u(&sA[b * PASZ + ar1 * 40 + ac1]), Z + (size_t)gr1 * DM + k0 + ac1);
        cpa16(s2u(&sB[b * PBSZ + br0 * 136 + bc0]), W + (size_t)(k0 + br0) * HD + n0 + bc0);
        cpa16(s2u(&sB[b * PBSZ + br1 * 136 + bc1]), W + (size_t)(k0 + br1) * HD + n0 + bc1);
    };

    float acc[4][4][4];
    #pragma unroll
    for (int i = 0; i < 4; i++)
        #pragma unroll
        for (int j = 0; j < 4; j++)
            #pragma unroll
            for (int k = 0; k < 4; k++) acc[i][j][k] = 0.f;

    prefetch(0, 0);
    CP_COMMIT();
    CP_WAIT0();
    __syncthreads();

    int cur = 0;
    for (int kt = 0; kt < 16; kt++) {
        if (kt < 15) { prefetch(kt + 1, cur ^ 1); CP_COMMIT(); }

        const __half* cA = sA + cur * PASZ;
        const __half* cB = sB + cur * PBSZ;

        #pragma unroll
        for (int kk = 0; kk < 32; kk += 16) {
            uint32_t a[4][4], b[4][2];
            #pragma unroll
            for (int mi = 0; mi < 4; mi++) {
                const int row = wm * 64 + mi * 16 + (lane & 15);
                const int col = kk + ((lane >> 4) << 3);
                ldsm4(a[mi], s2u(&cA[row * 40 + col]));
            }
            #pragma unroll
            for (int n16 = 0; n16 < 2; n16++) {
                const int row = kk + (lane & 15);
                const int col = wn * 32 + n16 * 16 + ((lane >> 4) << 3);
                uint32_t t[4];
                ldsm4t(t, s2u(&cB[row * 136 + col]));
                b[n16 * 2 + 0][0] = t[0]; b[n16 * 2 + 0][1] = t[1];
                b[n16 * 2 + 1][0] = t[2]; b[n16 * 2 + 1][1] = t[3];
            }
            #pragma unroll
            for (int mi = 0; mi < 4; mi++)
                #pragma unroll
                for (int nf = 0; nf < 4; nf++)
                    mma_f16(acc[mi][nf], a[mi], b[nf]);
        }

        if (kt < 15) {
            CP_WAIT0();
            __syncthreads();
            cur ^= 1;
        }
    }

    #pragma unroll
    for (int mi = 0; mi < 4; mi++) {
        const int r0 = m0 + wm * 64 + mi * 16 + (lane >> 2);
        #pragma unroll
        for (int nf = 0; nf < 4; nf++) {
            const int cc = n0 + wn * 32 + nf * 8 + ((lane & 3) << 1);
            #pragma unroll
            for (int rh = 0; rh < 2; rh++) {
                const int r = r0 + rh * 8;
                const float x0 = acc[mi][nf][rh * 2 + 0] * cscale;
                const float x1 = acc[mi][nf][rh * 2 + 1] * cscale;
                *(__half2*)&Cf[(size_t)r * HD + cc] = __floats2half2_rn(x0, x1);
            }
        }
    }
}

// =====================================================================
// Fused scores (single-term fp16 MMA) + gate + softmax partials + alpha means.
// CTA 64t x 64g, 256 threads (8 warps: wt=warp>>1 in 0..3, wg=warp&1),
// warp tile 16x32, 2 CTAs/SM. u_mean recovered from log(P) in amean.
// (R14 structure; only change vs R14: rcp.approx in the gate normalize.)
// =====================================================================
#define QMAT  9216                   // 64*72*2
#define STAGE (6 * QMAT)             // 3 Q + 3 K = 55296
#define SCORE_SMEM (2 * STAGE)       // 110592
#define LOG2E 1.4426950408889634f

__global__ __launch_bounds__(256, 2)
void score_cp(const float* __restrict__ gateW, const float* __restrict__ gateB,
              float* __restrict__ out_amean)
{
    extern __shared__ char sm[];

    const int tid = threadIdx.x;
    const int lane = tid & 31, warp = tid >> 5;
    const int wt = warp >> 1, wg = warp & 1;
    const int t0 = blockIdx.x * 64;
    const int g0 = blockIdx.y * 64;

    float acc_a0[16], acc_a1[16];
    #pragma unroll
    for (int i = 0; i < 16; i++) { acc_a0[i] = 0.f; acc_a1[i] = 0.f; }

    const int prow = tid >> 3, pc8 = (tid & 7) << 3;   // prow 0..31
    auto prefetch = [&](int h, int stg) {
        char* base = sm + stg * STAGE;
        #pragma unroll
        for (int e = 0; e < 3; e++) {
            char* qb = base + e * QMAT;
            char* kb = base + (3 + e) * QMAT;
            #pragma unroll
            for (int j = 0; j < 2; j++) {
                const int row = prow + j * 32;
                cpa16(s2u(qb + (row * 72 + pc8) * 2),
                      &g_Qf[e][0][0] + (size_t)(t0 + row) * HD + h * DK + pc8);
                cpa16(s2u(kb + (row * 72 + pc8) * 2),
                      &g_Kf[e][0][0] + (size_t)(g0 + row) * HD + h * DK + pc8);
            }
        }
    };

    prefetch(0, 0);
    CP_COMMIT();

    for (int h = 0; h < NH; h++) {
        const int stg = h & 1;
        CP_WAIT0();
        __syncthreads();
        if (h < NH - 1) { prefetch(h + 1, stg ^ 1); CP_COMMIT(); }

        const __half* tiles = (const __half*)(sm + stg * STAGE);

        float s[3][4][4];
        #pragma unroll
        for (int e = 0; e < 3; e++)
            #pragma unroll
            for (int c = 0; c < 4; c++)
                #pragma unroll
                for (int k = 0; k < 4; k++) s[e][c][k] = 0.f;

        #pragma unroll
        for (int e = 0; e < 3; e++) {
            const __half* Qf = tiles + e * (QMAT / 2);
            const __half* Kf = tiles + (3 + e) * (QMAT / 2);
            #pragma unroll
            for (int kk = 0; kk < 64; kk += 16) {
                const int col = kk + ((lane >> 4) << 3);
                uint32_t a[4];
                {
                    const int row = wt * 16 + (lane & 15);
                    ldsm4(a, s2u(&Qf[row * 72 + col]));
                }
                uint32_t b[4][2];
                #pragma unroll
                for (int n16 = 0; n16 < 2; n16++) {
                    const int row = wg * 32 + n16 * 16 + (lane & 15);
                    uint32_t kr[4];
                    ldsm4(kr, s2u(&Kf[row * 72 + col]));
                    b[n16 * 2 + 0][0] = kr[0]; b[n16 * 2 + 0][1] = kr[2];
                    b[n16 * 2 + 1][0] = kr[1]; b[n16 * 2 + 1][1] = kr[3];
                }
                #pragma unroll
                for (int nf = 0; nf < 4; nf++)
                    mma_f16(s[e][nf], a, b[nf]);
            }
        }

        // ---- gate + softmax-stats epilogue (relative to l2; log2 domain) ----
        const float w00 = gateW[h*9+0] * LOG2E, w01 = gateW[h*9+1] * LOG2E, w02 = gateW[h*9+2] * LOG2E;
        const float w10 = gateW[h*9+3] * LOG2E, w11 = gateW[h*9+4] * LOG2E, w12 = gateW[h*9+5] * LOG2E;
        const float w20 = gateW[h*9+6] * LOG2E, w21 = gateW[h*9+7] * LOG2E, w22 = gateW[h*9+8] * LOG2E;
        const float gb0 = gateB[h*3+0] * LOG2E, gb1 = gateB[h*3+1] * LOG2E, gb2 = gateB[h*3+2] * LOG2E;

        #pragma unroll
        for (int rh = 0; rh < 2; rh++) {
            const int tl = wt * 16 + (lane >> 2) + rh * 8;
            float zs = 0.f;
            #pragma unroll
            for (int nf = 0; nf < 4; nf++) {
                float eu2[2];
                #pragma unroll
                for (int p = 0; p < 2; p++) {
                    const int fi = rh * 8 + nf * 2 + p;
                    const float s0 = s[0][nf][rh * 2 + p];
                    const float s1 = s[1][nf][rh * 2 + p];
                    const float s2 = s[2][nf][rh * 2 + p];
                    const float l0 = fmaf(s0, w00, fmaf(s1, w10, fmaf(s2, w20, gb0)));
                    const float l1 = fmaf(s0, w01, fmaf(s1, w11, fmaf(s2, w21, gb1)));
                    const float l2 = fmaf(s0, w02, fmaf(s1, w12, fmaf(s2, w22, gb2)));
                    const float r0 = exp2f(l0 - l2);
                    const float r1 = exp2f(l1 - l2);
                    const float inv = frcp(r0 + r1 + 1.0f);
                    const float u = fmaf(r0, s0, fmaf(r1, s1, s2)) * inv;
                    const float eu = exp2f(u * LOG2E);
                    eu2[p] = eu;
                    zs += eu;
                    acc_a0[fi] += r0 * inv;
                    acc_a1[fi] += r1 * inv;
                }
                __half2 ph = __floats2half2_rn(eu2[0], eu2[1]);
                *(__half2*)&g_P[h][t0 + tl][g0 + wg * 32 + nf * 8 + ((lane & 3) << 1)] = ph;
            }
            zs += __shfl_xor_sync(0xffffffffu, zs, 1);
            zs += __shfl_xor_sync(0xffffffffu, zs, 2);
            if ((lane & 3) == 0)
                g_part[h][t0 + tl][blockIdx.y * 2 + wg] = zs;
        }
    }

    // alpha means from register accumulators
    #pragma unroll
    for (int rh = 0; rh < 2; rh++) {
        const int tl = wt * 16 + (lane >> 2) + rh * 8;
        #pragma unroll
        for (int nf = 0; nf < 4; nf++) {
            const int gl = wg * 32 + nf * 8 + ((lane & 3) << 1);
            const size_t o = (size_t)(t0 + tl) * NG + g0 + gl;
            const int f0 = rh * 8 + nf * 2;
            const float a00 = acc_a0[f0]     * 0.125f;
            const float a10 = acc_a1[f0]     * 0.125f;
            const float a01 = acc_a0[f0 + 1] * 0.125f;
            const float a11 = acc_a1[f0 + 1] * 0.125f;
            float2* ap = (float2*)(out_amean + o * 3);
            ap[0] = make_float2(a00, a10);
            ap[1] = make_float2(1.0f - a00 - a10, a01);
            ap[2] = make_float2(a11, 1.0f - a01 - a11);
        }
    }
}

// =====================================================================
// Reduce per-chunk partial sums -> 1/Z per (h, t). One warp per row.
// =====================================================================
__global__ void stats_kernel()
{
    const int gt   = blockIdx.x * blockDim.x + threadIdx.x;
    const int wid  = gt >> 5;
    const int lane = threadIdx.x & 31;
    if (wid >= NH * NT) return;
    const int h = wid >> 9;
    const int t = wid & (NT - 1);

    float z = 0.f;
    #pragma unroll
    for (int j = 0; j < 16; j++)
        z += g_part[h][t][lane + 32 * j];
    #pragma unroll
    for (int off = 16; off; off >>= 1)
        z += __shfl_xor_sync(0xffffffffu, z, off);
    if (lane == 0) g_invz[h][t] = 1.0f / z;
}

// =====================================================================
// A_mean[t,g] = (1/8) * sum_h p / Z;  u_mean[t,g] = (1/8) * sum_h log(p).
// =====================================================================
__global__ void amean_kernel(float* __restrict__ out_A, float* __restrict__ out_u)
{
    const int t = blockIdx.y;
    const int g = (blockIdx.x * 256 + threadIdx.x) * 4;
    __shared__ float st[NH];
    if (threadIdx.x < NH) st[threadIdx.x] = g_invz[threadIdx.x][t];
    __syncthreads();
    float4 acc = make_float4(0.f, 0.f, 0.f, 0.f);
    float4 um  = make_float4(0.f, 0.f, 0.f, 0.f);
    #pragma unroll
    for (int h = 0; h < NH; h++) {
        const __half2* pp = (const __half2*)&g_P[h][t][g];
        const float2 f0 = __half22float2(pp[0]);
        const float2 f1 = __half22float2(pp[1]);
        const float iz = st[h];
        acc.x = fmaf(f0.x, iz, acc.x);
        acc.y = fmaf(f0.y, iz, acc.y);
        acc.z = fmaf(f1.x, iz, acc.z);
        acc.w = fmaf(f1.y, iz, acc.w);
        um.x += __log2f(f0.x);
        um.y += __log2f(f0.y);
        um.z += __log2f(f1.x);
        um.w += __log2f(f1.y);
    }
    acc.x *= 0.125f; acc.y *= 0.125f; acc.z *= 0.125f; acc.w *= 0.125f;
    const float us = 0.125f / LOG2E;
    um.x *= us; um.y *= us; um.z *= us; um.w *= us;
    *(float4*)&out_A[(size_t)t * NG + g] = acc;
    *(float4*)&out_u[(size_t)t * NG + g] = um;
}

// =====================================================================
extern "C" void kernel_launch(void* const* d_in, const int* in_sizes, int n_in,
                              void* d_out, int out_size)
{
    const float* H_TF   = (const float*)d_in[0];
    const float* H_G    = (const float*)d_in[1];
    const float* z_exp  = (const float*)d_in[2];
    const float* z_seq  = (const float*)d_in[3];
    const float* z_txt  = (const float*)d_in[4];
    const int*   tf_idx = (const int*)  d_in[5];
    const float* Wq_seq = (const float*)d_in[6];
    const float* Wk_seq = (const float*)d_in[7];
    const float* Wq_exp = (const float*)d_in[8];
    const float* Wk_exp = (const float*)d_in[9];
    const float* Wq_txt = (const float*)d_in[10];
    const float* Wk_txt = (const float*)d_in[11];
    const float* gateW  = (const float*)d_in[12];
    const float* gateB  = (const float*)d_in[13];
    float* out = (float*)d_out;

    float* out_A  = out + (size_t)NT * DM + (size_t)NG * DM;
    float* out_u  = out_A + (size_t)NT * NG;
    float* out_al = out_u + (size_t)NT * NG;

    cudaFuncSetAttribute(proj_mma, cudaFuncAttributeMaxDynamicSharedMemorySize, PROJ_SMEM);
    cudaFuncSetAttribute(score_cp, cudaFuncAttributeMaxDynamicSharedMemorySize, SCORE_SMEM);

    // evidence order: e0 = seq (bind), e1 = exp (coexpr), e2 = txt (know)
    split_kernel<<<4096, 256>>>((const float4*)z_seq, (const float4*)z_exp, (const float4*)z_txt,
                                (const float4*)Wk_seq, (const float4*)Wk_exp, (const float4*)Wk_txt,
                                (const float4*)Wq_seq, (const float4*)Wq_exp, (const float4*)Wq_txt,
                                (const float4*)H_TF, (const float4*)H_G, (float4*)out);

    proj_mma<<<dim3(NG / 128, 4, 6), 256, PROJ_SMEM>>>(tf_idx);

    score_cp<<<dim3(NT / 64, NG / 64), 256, SCORE_SMEM>>>(gateW, gateB, out_al);

    stats_kernel<<<(NH * NT * 32) / 256, 256>>>();

    amean_kernel<<<dim3(NG / 1024, NT), 256>>>(out_A, out_u);
}

// round 17
// speedup vs baseline: 1.1017x; 1.0012x over previous
#include <cuda_runtime.h>
#include <cuda_bf16.h>
#include <cuda_fp16.h>
#include <cstdint>
#include <cstddef>

#define NT 512
#define NG 16384
#define DM 512
#define NH 8
#define DK 64
#define HD 512

// ---------------- scratch (static device memory) ----------------
__device__ __half g_Zf[3][NG][DM];                   // inputs, fp16
__device__ __half g_Wf[6][DM][HD];                   // 0-2: Wk_{seq,exp,txt}, 3-5: Wq_*
__device__ __half g_Qf[3][NT][HD];                   // Q * 0.125, fp16
__device__ __half g_Kf[3][NG][HD];                   // K, fp16
__device__ __half g_P[NH][NT][NG];                   // exp(u) in fp16
__device__ float g_part[NH][NT][512];                // per-32g-chunk sum(exp(u))
__device__ float g_invz[NH][NT];

// ---------------- ptx helpers ----------------
__device__ __forceinline__ uint32_t s2u(const void* p) {
    return (uint32_t)__cvta_generic_to_shared(p);
}
__device__ __forceinline__ void ldsm4(uint32_t* r, uint32_t a) {
    asm volatile("ldmatrix.sync.aligned.m8n8.x4.shared.b16 {%0,%1,%2,%3},[%4];\n"
                 : "=r"(r[0]), "=r"(r[1]), "=r"(r[2]), "=r"(r[3]) : "r"(a));
}
__device__ __forceinline__ void ldsm4t(uint32_t* r, uint32_t a) {
    asm volatile("ldmatrix.sync.aligned.m8n8.x4.trans.shared.b16 {%0,%1,%2,%3},[%4];\n"
                 : "=r"(r[0]), "=r"(r[1]), "=r"(r[2]), "=r"(r[3]) : "r"(a));
}
__device__ __forceinline__ void mma_f16(float* d, const uint32_t* a, const uint32_t* b) {
    asm volatile("mma.sync.aligned.m16n8k16.row.col.f32.f16.f16.f32 "
                 "{%0,%1,%2,%3},{%4,%5,%6,%7},{%8,%9},{%0,%1,%2,%3};\n"
                 : "+f"(d[0]), "+f"(d[1]), "+f"(d[2]), "+f"(d[3])
                 : "r"(a[0]), "r"(a[1]), "r"(a[2]), "r"(a[3]), "r"(b[0]), "r"(b[1]));
}
__device__ __forceinline__ void cpa16(uint32_t s, const void* g) {
    asm volatile("cp.async.cg.shared.global [%0], [%1], 16;\n" :: "r"(s), "l"(g) : "memory");
}
__device__ __forceinline__ float frcp(float x) {
    float r;
    asm("rcp.approx.f32 %0, %1;" : "=f"(r) : "f"(x));
    return r;
}
#define CP_COMMIT() asm volatile("cp.async.commit_group;\n" ::: "memory")
#define CP_WAIT0()  asm volatile("cp.async.wait_group 0;\n" ::: "memory")

// =====================================================================
// Convert fp32 -> fp16 for z (3) and W (6), plus passthrough copies.
// =====================================================================
__global__ void split_kernel(const float4* __restrict__ za, const float4* __restrict__ zb,
                             const float4* __restrict__ zc,
                             const float4* __restrict__ w0, const float4* __restrict__ w1,
                             const float4* __restrict__ w2, const float4* __restrict__ w3,
                             const float4* __restrict__ w4, const float4* __restrict__ w5,
                             const float4* __restrict__ htf, const float4* __restrict__ hg,
                             float4* __restrict__ outc)
{
    const int NZ4 = NG * DM / 4;
    const int NW4 = DM * HD / 4;
    const int NA4 = NT * DM / 4;
    const int NC4 = NA4 + NG * DM / 4;
    const int TOT = 3 * NZ4 + 6 * NW4 + NC4;
    for (int i = blockIdx.x * blockDim.x + threadIdx.x; i < TOT; i += gridDim.x * blockDim.x) {
        if (i >= 3 * NZ4 + 6 * NW4) {
            const int j = i - 3 * NZ4 - 6 * NW4;
            outc[j] = (j < NA4) ? htf[j] : hg[j - NA4];
            continue;
        }
        float4 v; __half2* dst;
        if (i < 3 * NZ4) {
            const int e = i / NZ4, j = i - e * NZ4;
            v = (e == 0 ? za : e == 1 ? zb : zc)[j];
            dst = (__half2*)&g_Zf[e][0][0] + (size_t)j * 2;
        } else {
            const int k = i - 3 * NZ4;
            const int w = k / NW4, j = k - w * NW4;
            const float4* src = w == 0 ? w0 : w == 1 ? w1 : w == 2 ? w2 : w == 3 ? w3 : w == 4 ? w4 : w5;
            v = src[j];
            dst = (__half2*)&g_Wf[w][0][0] + (size_t)j * 2;
        }
        dst[0] = __floats2half2_rn(v.x, v.y);
        dst[1] = __floats2half2_rn(v.z, v.w);
    }
}

// =====================================================================
// Projection GEMM, single-term fp16 MMA, cp.async double-buffered.
// Merged K+Q launch (z >= 3 -> Q). (unchanged known-good)
// =====================================================================
#define PASZ (128 * 40)
#define PBSZ (32 * 136)
#define PROJ_SMEM ((2 * PASZ + 2 * PBSZ) * 2)   // 37888 bytes

__global__ __launch_bounds__(256, 2)
void proj_mma(const int* __restrict__ idx)
{
    const int isQ = blockIdx.z >= 3;
    const int e = isQ ? (blockIdx.z - 3) : blockIdx.z;
    const int m0 = blockIdx.x * 128, n0 = blockIdx.y * 128;
    if (isQ && m0 >= NT) return;
    const __half* Z = &g_Zf[e][0][0];
    const __half* W = &g_Wf[(isQ ? 3 : 0) + e][0][0];
    __half* Cf = isQ ? &g_Qf[e][0][0] : &g_Kf[e][0][0];
    const float cscale = isQ ? 0.125f : 1.0f;

    extern __shared__ char sm[];
    __half* sA = (__half*)sm;
    __half* sB = sA + 2 * PASZ;

    const int tid = threadIdx.x;
    const int lane = tid & 31, warp = tid >> 5;
    const int wm = warp >> 2, wn = warp & 3;

    const int l0 = tid, l1 = tid + 256;
    const int ar0 = l0 >> 2, ac0 = (l0 & 3) << 3;
    const int ar1 = l1 >> 2, ac1 = (l1 & 3) << 3;
    const int gr0 = isQ ? idx[m0 + ar0] : (m0 + ar0);
    const int gr1 = isQ ? idx[m0 + ar1] : (m0 + ar1);
    const int br0 = l0 >> 4, bc0 = (l0 & 15) << 3;
    const int br1 = l1 >> 4, bc1 = (l1 & 15) << 3;

    auto prefetch = [&](int kt, int b) {
        const int k0 = kt * 32;
        cpa16(s2u(&sA[b * PASZ + ar0 * 40 + ac0]), Z + (size_t)gr0 * DM + k0 + ac0);
        cpa16(s2u(&sA[b * PASZ + ar1 * 40 + ac1]), Z + (size_t)gr1 * DM + k0 + ac1);
        cpa16(s2u(&sB[b * PBSZ + br0 * 136 + bc0]), W + (size_t)(k0 + br0) * HD + n0 + bc0);
        cpa16(s2u(&sB[b * PBSZ + br1 * 136 + bc1]), W + (size_t)(k0 + br1) * HD + n0 + bc1);
    };

    float acc[4][4][4];
    #pragma unroll
    for (int i = 0; i < 4; i++)
        #pragma unroll
        for (int j = 0; j < 4; j++)
            #pragma unroll
            for (int k = 0; k < 4; k++) acc[i][j][k] = 0.f;

    prefetch(0, 0);
    CP_COMMIT();
    CP_WAIT0();
    __syncthreads();

    int cur = 0;
    for (int kt = 0; kt < 16; kt++) {
        if (kt < 15) { prefetch(kt + 1, cur ^ 1); CP_COMMIT(); }

        const __half* cA = sA + cur * PASZ;
        const __half* cB = sB + cur * PBSZ;

        #pragma unroll
        for (int kk = 0; kk < 32; kk += 16) {
            uint32_t a[4][4], b[4][2];
            #pragma unroll
            for (int mi = 0; mi < 4; mi++) {
                const int row = wm * 64 + mi * 16 + (lane & 15);
                const int col = kk + ((lane >> 4) << 3);
                ldsm4(a[mi], s2u(&cA[row * 40 + col]));
            }
            #pragma unroll
            for (int n16 = 0; n16 < 2; n16++) {
                const int row = kk + (lane & 15);
                const int col = wn * 32 + n16 * 16 + ((lane >> 4) << 3);
                uint32_t t[4];
                ldsm4t(t, s2u(&cB[row * 136 + col]));
                b[n16 * 2 + 0][0] = t[0]; b[n16 * 2 + 0][1] = t[1];
                b[n16 * 2 + 1][0] = t[2]; b[n16 * 2 + 1][1] = t[3];
            }
            #pragma unroll
            for (int mi = 0; mi < 4; mi++)
                #pragma unroll
                for (int nf = 0; nf < 4; nf++)
                    mma_f16(acc[mi][nf], a[mi], b[nf]);
        }

        if (kt < 15) {
            CP_WAIT0();
            __syncthreads();
            cur ^= 1;
        }
    }

    #pragma unroll
    for (int mi = 0; mi < 4; mi++) {
        const int r0 = m0 + wm * 64 + mi * 16 + (lane >> 2);
        #pragma unroll
        for (int nf = 0; nf < 4; nf++) {
            const int cc = n0 + wn * 32 + nf * 8 + ((lane & 3) << 1);
            #pragma unroll
            for (int rh = 0; rh < 2; rh++) {
                const int r = r0 + rh * 8;
                const float x0 = acc[mi][nf][rh * 2 + 0] * cscale;
                const float x1 = acc[mi][nf][rh * 2 + 1] * cscale;
                *(__half2*)&Cf[(size_t)r * HD + cc] = __floats2half2_rn(x0, x1);
            }
        }
    }
}

// =====================================================================
// Fused scores (single-term fp16 MMA) + gate + softmax partials + alpha means.
// CTA 64t x 64g, 256 threads (8 warps: wt=warp>>1 in 0..3, wg=warp&1),
// warp tile 16x32, 2 CTAs/SM. u_mean recovered from log(P) in amean.
// (unchanged from R16 known-good)
// =====================================================================
#define QMAT  9216                   // 64*72*2
#define STAGE (6 * QMAT)             // 3 Q + 3 K = 55296
#define SCORE_SMEM (2 * STAGE)       // 110592
#define LOG2E 1.4426950408889634f

__global__ __launch_bounds__(256, 2)
void score_cp(const float* __restrict__ gateW, const float* __restrict__ gateB,
              float* __restrict__ out_amean)
{
    extern __shared__ char sm[];

    const int tid = threadIdx.x;
    const int lane = tid & 31, warp = tid >> 5;
    const int wt = warp >> 1, wg = warp & 1;
    const int t0 = blockIdx.x * 64;
    const int g0 = blockIdx.y * 64;

    float acc_a0[16], acc_a1[16];
    #pragma unroll
    for (int i = 0; i < 16; i++) { acc_a0[i] = 0.f; acc_a1[i] = 0.f; }

    const int prow = tid >> 3, pc8 = (tid & 7) << 3;   // prow 0..31
    auto prefetch = [&](int h, int stg) {
        char* base = sm + stg * STAGE;
        #pragma unroll
        for (int e = 0; e < 3; e++) {
            char* qb = base + e * QMAT;
            char* kb = base + (3 + e) * QMAT;
            #pragma unroll
            for (int j = 0; j < 2; j++) {
                const int row = prow + j * 32;
                cpa16(s2u(qb + (row * 72 + pc8) * 2),
                      &g_Qf[e][0][0] + (size_t)(t0 + row) * HD + h * DK + pc8);
                cpa16(s2u(kb + (row * 72 + pc8) * 2),
                      &g_Kf[e][0][0] + (size_t)(g0 + row) * HD + h * DK + pc8);
            }
        }
    };

    prefetch(0, 0);
    CP_COMMIT();

    for (int h = 0; h < NH; h++) {
        const int stg = h & 1;
        CP_WAIT0();
        __syncthreads();
        if (h < NH - 1) { prefetch(h + 1, stg ^ 1); CP_COMMIT(); }

        const __half* tiles = (const __half*)(sm + stg * STAGE);

        float s[3][4][4];
        #pragma unroll
        for (int e = 0; e < 3; e++)
            #pragma unroll
            for (int c = 0; c < 4; c++)
                #pragma unroll
                for (int k = 0; k < 4; k++) s[e][c][k] = 0.f;

        #pragma unroll
        for (int e = 0; e < 3; e++) {
            const __half* Qf = tiles + e * (QMAT / 2);
            const __half* Kf = tiles + (3 + e) * (QMAT / 2);
            #pragma unroll
            for (int kk = 0; kk < 64; kk += 16) {
                const int col = kk + ((lane >> 4) << 3);
                uint32_t a[4];
                {
                    const int row = wt * 16 + (lane & 15);
                    ldsm4(a, s2u(&Qf[row * 72 + col]));
                }
                uint32_t b[4][2];
                #pragma unroll
                for (int n16 = 0; n16 < 2; n16++) {
                    const int row = wg * 32 + n16 * 16 + (lane & 15);
                    uint32_t kr[4];
                    ldsm4(kr, s2u(&Kf[row * 72 + col]));
                    b[n16 * 2 + 0][0] = kr[0]; b[n16 * 2 + 0][1] = kr[2];
                    b[n16 * 2 + 1][0] = kr[1]; b[n16 * 2 + 1][1] = kr[3];
                }
                #pragma unroll
                for (int nf = 0; nf < 4; nf++)
                    mma_f16(s[e][nf], a, b[nf]);
            }
        }

        // ---- gate + softmax-stats epilogue (relative to l2; log2 domain) ----
        const float w00 = gateW[h*9+0] * LOG2E, w01 = gateW[h*9+1] * LOG2E, w02 = gateW[h*9+2] * LOG2E;
        const float w10 = gateW[h*9+3] * LOG2E, w11 = gateW[h*9+4] * LOG2E, w12 = gateW[h*9+5] * LOG2E;
        const float w20 = gateW[h*9+6] * LOG2E, w21 = gateW[h*9+7] * LOG2E, w22 = gateW[h*9+8] * LOG2E;
        const float gb0 = gateB[h*3+0] * LOG2E, gb1 = gateB[h*3+1] * LOG2E, gb2 = gateB[h*3+2] * LOG2E;

        #pragma unroll
        for (int rh = 0; rh < 2; rh++) {
            const int tl = wt * 16 + (lane >> 2) + rh * 8;
            float zs = 0.f;
            #pragma unroll
            for (int nf = 0; nf < 4; nf++) {
                float eu2[2];
                #pragma unroll
                for (int p = 0; p < 2; p++) {
                    const int fi = rh * 8 + nf * 2 + p;
                    const float s0 = s[0][nf][rh * 2 + p];
                    const float s1 = s[1][nf][rh * 2 + p];
                    const float s2 = s[2][nf][rh * 2 + p];
                    const float l0 = fmaf(s0, w00, fmaf(s1, w10, fmaf(s2, w20, gb0)));
                    const float l1 = fmaf(s0, w01, fmaf(s1, w11, fmaf(s2, w21, gb1)));
                    const float l2 = fmaf(s0, w02, fmaf(s1, w12, fmaf(s2, w22, gb2)));
                    const float r0 = exp2f(l0 - l2);
                    const float r1 = exp2f(l1 - l2);
                    const float inv = frcp(r0 + r1 + 1.0f);
                    const float u = fmaf(r0, s0, fmaf(r1, s1, s2)) * inv;
                    const float eu = exp2f(u * LOG2E);
                    eu2[p] = eu;
                    zs += eu;
                    acc_a0[fi] += r0 * inv;
                    acc_a1[fi] += r1 * inv;
                }
                __half2 ph = __floats2half2_rn(eu2[0], eu2[1]);
                *(__half2*)&g_P[h][t0 + tl][g0 + wg * 32 + nf * 8 + ((lane & 3) << 1)] = ph;
            }
            zs += __shfl_xor_sync(0xffffffffu, zs, 1);
            zs += __shfl_xor_sync(0xffffffffu, zs, 2);
            if ((lane & 3) == 0)
                g_part[h][t0 + tl][blockIdx.y * 2 + wg] = zs;
        }
    }

    // alpha means from register accumulators
    #pragma unroll
    for (int rh = 0; rh < 2; rh++) {
        const int tl = wt * 16 + (lane >> 2) + rh * 8;
        #pragma unroll
        for (int nf = 0; nf < 4; nf++) {
            const int gl = wg * 32 + nf * 8 + ((lane & 3) << 1);
            const size_t o = (size_t)(t0 + tl) * NG + g0 + gl;
            const int f0 = rh * 8 + nf * 2;
            const float a00 = acc_a0[f0]     * 0.125f;
            const float a10 = acc_a1[f0]     * 0.125f;
            const float a01 = acc_a0[f0 + 1] * 0.125f;
            const float a11 = acc_a1[f0 + 1] * 0.125f;
            float2* ap = (float2*)(out_amean + o * 3);
            ap[0] = make_float2(a00, a10);
            ap[1] = make_float2(1.0f - a00 - a10, a01);
            ap[2] = make_float2(a11, 1.0f - a01 - a11);
        }
    }
}

// =====================================================================
// Reduce per-chunk partial sums -> 1/Z per (h, t). One warp per row.
// =====================================================================
__global__ void stats_kernel()
{
    const int gt   = blockIdx.x * blockDim.x + threadIdx.x;
    const int wid  = gt >> 5;
    const int lane = threadIdx.x & 31;
    if (wid >= NH * NT) return;
    const int h = wid >> 9;
    const int t = wid & (NT - 1);

    float z = 0.f;
    #pragma unroll
    for (int j = 0; j < 16; j++)
        z += g_part[h][t][lane + 32 * j];
    #pragma unroll
    for (int off = 16; off; off >>= 1)
        z += __shfl_xor_sync(0xffffffffu, z, off);
    if (lane == 0) g_invz[h][t] = 1.0f / z;
}

// =====================================================================
// A_mean[t,g] = (1/8) * sum_h p / Z;  u_mean[t,g] = (1/8) * sum_h log(p).
// 8 elements/thread: one LDG.128 per h, 8 independent chains (MLP).
// =====================================================================
__global__ void amean_kernel(float* __restrict__ out_A, float* __restrict__ out_u)
{
    const int t = blockIdx.y;
    const int g = (blockIdx.x * 256 + threadIdx.x) * 8;
    __shared__ float st[NH];
    if (threadIdx.x < NH) st[threadIdx.x] = g_invz[threadIdx.x][t];
    __syncthreads();

    float acc[8], um[8];
    #pragma unroll
    for (int i = 0; i < 8; i++) { acc[i] = 0.f; um[i] = 0.f; }

    #pragma unroll
    for (int h = 0; h < NH; h++) {
        const uint4 pk = *(const uint4*)&g_P[h][t][g];
        const uint32_t pw[4] = { pk.x, pk.y, pk.z, pk.w };
        const float iz = st[h];
        #pragma unroll
        for (int j = 0; j < 4; j++) {
            const float2 f = __half22float2(*(const __half2*)&pw[j]);
            acc[j * 2 + 0] = fmaf(f.x, iz, acc[j * 2 + 0]);
            acc[j * 2 + 1] = fmaf(f.y, iz, acc[j * 2 + 1]);
            um[j * 2 + 0] += __log2f(f.x);
            um[j * 2 + 1] += __log2f(f.y);
        }
    }

    const float us = 0.125f / LOG2E;
    float4 a0, a1, u0, u1;
    a0.x = acc[0] * 0.125f; a0.y = acc[1] * 0.125f; a0.z = acc[2] * 0.125f; a0.w = acc[3] * 0.125f;
    a1.x = acc[4] * 0.125f; a1.y = acc[5] * 0.125f; a1.z = acc[6] * 0.125f; a1.w = acc[7] * 0.125f;
    u0.x = um[0] * us; u0.y = um[1] * us; u0.z = um[2] * us; u0.w = um[3] * us;
    u1.x = um[4] * us; u1.y = um[5] * us; u1.z = um[6] * us; u1.w = um[7] * us;
    float4* pa = (float4*)&out_A[(size_t)t * NG + g];
    float4* pu = (float4*)&out_u[(size_t)t * NG + g];
    pa[0] = a0; pa[1] = a1;
    pu[0] = u0; pu[1] = u1;
}

// =====================================================================
extern "C" void kernel_launch(void* const* d_in, const int* in_sizes, int n_in,
                              void* d_out, int out_size)
{
    const float* H_TF   = (const float*)d_in[0];
    const float* H_G    = (const float*)d_in[1];
    const float* z_exp  = (const float*)d_in[2];
    const float* z_seq  = (const float*)d_in[3];
    const float* z_txt  = (const float*)d_in[4];
    const int*   tf_idx = (const int*)  d_in[5];
    const float* Wq_seq = (const float*)d_in[6];
    const float* Wk_seq = (const float*)d_in[7];
    const float* Wq_exp = (const float*)d_in[8];
    const float* Wk_exp = (const float*)d_in[9];
    const float* Wq_txt = (const float*)d_in[10];
    const float* Wk_txt = (const float*)d_in[11];
    const float* gateW  = (const float*)d_in[12];
    const float* gateB  = (const float*)d_in[13];
    float* out = (float*)d_out;

    float* out_A  = out + (size_t)NT * DM + (size_t)NG * DM;
    float* out_u  = out_A + (size_t)NT * NG;
    float* out_al = out_u + (size_t)NT * NG;

    cudaFuncSetAttribute(proj_mma, cudaFuncAttributeMaxDynamicSharedMemorySize, PROJ_SMEM);
    cudaFuncSetAttribute(score_cp, cudaFuncAttributeMaxDynamicSharedMemorySize, SCORE_SMEM);

    // evidence order: e0 = seq (bind), e1 = exp (coexpr), e2 = txt (know)
    split_kernel<<<4096, 256>>>((const float4*)z_seq, (const float4*)z_exp, (const float4*)z_txt,
                                (const float4*)Wk_seq, (const float4*)Wk_exp, (const float4*)Wk_txt,
                                (const float4*)Wq_seq, (const float4*)Wq_exp, (const float4*)Wq_txt,
                                (const float4*)H_TF, (const float4*)H_G, (float4*)out);

    proj_mma<<<dim3(NG / 128, 4, 6), 256, PROJ_SMEM>>>(tf_idx);

    score_cp<<<dim3(NT / 64, NG / 64), 256, SCORE_SMEM>>>(gateW, gateB, out_al);

    stats_kernel<<<(NH * NT * 32) / 256, 256>>>();

    amean_kernel<<<dim3(NG / 2048, NT), 256>>>(out_A, out_u);
}